// round 9
// baseline (speedup 1.0000x reference)
#include <cuda_runtime.h>
#include <cstdint>

#define BT   192
#define SEQ  207
#define CC   128
#define RED  64
#define DIN  128
#define DS   16
#define XD   36
#define NROWS (BT*SEQ)   // 39744

// ---------------- scratch (no allocation allowed) ----------------
__device__ float g_h0  [BT*SEQ*RED];   // ~10.2 MB
__device__ float g_dir0[BT*SEQ*RED];
__device__ float g_dir1[BT*SEQ*RED];

struct MambaW {
    const float *inproj, *convw, *convb, *xproj, *dtw, *dtb, *Alog, *D, *outproj;
};

// =================================================================
// Kernel 1: h0 = LN_256(concat(x,qk)) @ in_w + in_b     (rows x 64)
// =================================================================
#define R1 16
#define PRE_SMEM ((16384 + R1*257)*4)

__global__ void __launch_bounds__(256) pre_kernel(
    const float* __restrict__ x, const float* __restrict__ qk,
    const float* __restrict__ lnw, const float* __restrict__ lnb,
    const float* __restrict__ W,   const float* __restrict__ Wb)
{
    extern __shared__ float sm[];
    float* s_w  = sm;            // 256*64 floats
    float* s_ln = sm + 16384;    // R1 rows * 257 (pad)
    int tid = threadIdx.x;

    {   // stage in_w (64 KB) into SMEM
        const float4* ws = (const float4*)W;
        float4* wd = (float4*)s_w;
        for (int i = tid; i < 4096; i += 256) wd[i] = ws[i];
    }

    int base = blockIdx.x * R1;
    int warp = tid >> 5, lane = tid & 31;

    for (int rr = 0; rr < 2; rr++) {
        int r = warp * 2 + rr;
        size_t row = (size_t)(base + r);
        const float* xr = x  + row * CC;
        const float* qr = qk + row * CC;
        float v[8]; float sum = 0.f, sq = 0.f;
#pragma unroll
        for (int k = 0; k < 8; k++) {
            int i = lane + 32*k;
            float val = (i < CC) ? xr[i] : qr[i - CC];
            v[k] = val; sum += val; sq += val*val;
        }
#pragma unroll
        for (int off = 16; off; off >>= 1) {
            sum += __shfl_xor_sync(0xffffffffu, sum, off);
            sq  += __shfl_xor_sync(0xffffffffu, sq,  off);
        }
        float mean = sum * (1.f/256.f);
        float var  = sq  * (1.f/256.f) - mean*mean;
        float rstd = rsqrtf(var + 1e-5f);
#pragma unroll
        for (int k = 0; k < 8; k++) {
            int i = lane + 32*k;
            s_ln[r*257 + i] = (v[k]-mean)*rstd*lnw[i] + lnb[i];
        }
    }
    __syncthreads();

    // GEMM 256 -> 64 : thread = (row r, 4-col group j4)
    int r = tid >> 4, j4 = tid & 15;
    int row = base + r;
    float4 acc = ((const float4*)Wb)[j4];
    const float4* wd = (const float4*)s_w;
#pragma unroll 8
    for (int i = 0; i < 256; i++) {
        float lv = s_ln[r*257 + i];
        float4 w4 = wd[i*16 + j4];
        acc.x = fmaf(lv, w4.x, acc.x);
        acc.y = fmaf(lv, w4.y, acc.y);
        acc.z = fmaf(lv, w4.z, acc.z);
        acc.w = fmaf(lv, w4.w, acc.w);
    }
    ((float4*)g_h0)[(size_t)row*16 + j4] = acc;
}

// =================================================================
// Kernel 2: one CTA per (b, direction). Whole mamba branch fused.
// =================================================================
#define SM_U   (SEQ*RED)             // 13248
#define SM_XDo (SM_U + SEQ*DIN)      // 39744
#define SM_XPo (SM_XDo + SEQ*XD)     // 47196
#define SM_TOT (SM_XPo + DIN*XD)     // 51804 floats
#define MAMBA_SMEM (SM_TOT*4)        // 207216 B

__global__ void __launch_bounds__(256, 1) mamba_kernel(MambaW wf, MambaW wb)
{
    extern __shared__ float sm[];
    float* sh_h0 = sm;
    float* sh_u  = sm + SM_U;
    float* sh_xd = sm + SM_XDo;
    float* sh_xp = sm + SM_XPo;
    float* sh_op = sm + SM_XDo;      // reuses xdbl+xproj region after scan (12060 >= 8192)

    int b   = blockIdx.x % BT;
    int dir = blockIdx.x / BT;
    MambaW p = dir ? wb : wf;
    float* outbuf = dir ? g_dir1 : g_dir0;
    int tid = threadIdx.x;

    // ---- A: load h0 (reversed for bw) + xproj into SMEM ----
    const float* h0row = g_h0 + (size_t)b * SEQ * RED;
    for (int i = tid; i < SEQ*RED; i += 256) {
        int t = i >> 6, k = i & 63;
        int pt = dir ? (SEQ-1-t) : t;
        sh_h0[i] = h0row[pt*RED + k];
    }
    for (int i = tid; i < DIN*XD; i += 256) sh_xp[i] = p.xproj[i];
    __syncthreads();

    // ---- B: u_pre = h0 @ inproj[:, :128] ----
    {
        int d = tid & 127, tg = tid >> 7;
        float wcol[RED];
#pragma unroll
        for (int k = 0; k < RED; k++) wcol[k] = p.inproj[k*256 + d];
        for (int t = tg; t < SEQ; t += 2) {
            const float4* hr = (const float4*)(sh_h0 + t*RED);
            float acc = 0.f;
#pragma unroll
            for (int q = 0; q < 16; q++) {
                float4 h4 = hr[q];
                acc = fmaf(h4.x, wcol[4*q+0], acc);
                acc = fmaf(h4.y, wcol[4*q+1], acc);
                acc = fmaf(h4.z, wcol[4*q+2], acc);
                acc = fmaf(h4.w, wcol[4*q+3], acc);
            }
            sh_u[t*DIN + d] = acc;
        }
    }
    __syncthreads();

    // ---- C: depthwise causal conv(K=4) + silu, in place ----
    {
        int d = tid & 127, half = tid >> 7;
        float w0 = p.convw[d*4+0], w1 = p.convw[d*4+1];
        float w2 = p.convw[d*4+2], w3 = p.convw[d*4+3];
        float bb = p.convb[d];
        int t0 = half ? 104 : 0;
        int t1 = half ? SEQ : 104;
        float p3 = (t0 >= 3) ? sh_u[(t0-3)*DIN + d] : 0.f;
        float p2 = (t0 >= 2) ? sh_u[(t0-2)*DIN + d] : 0.f;
        float p1 = (t0 >= 1) ? sh_u[(t0-1)*DIN + d] : 0.f;
        __syncthreads();   // boundary pre-conv reads done before any overwrite
        for (int t = t0; t < t1; t++) {
            float cur = sh_u[t*DIN + d];
            float v = fmaf(w0,p3, fmaf(w1,p2, fmaf(w2,p1, fmaf(w3,cur, bb))));
            v = v / (1.f + __expf(-v));         // silu
            sh_u[t*DIN + d] = v;
            p3 = p2; p2 = p1; p1 = cur;
        }
    }
    __syncthreads();

    // ---- D: xdbl = u @ xproj  (one thread per t, 36 accumulators) ----
    if (tid < SEQ) {
        int t = tid;
        float acc[XD];
#pragma unroll
        for (int j = 0; j < XD; j++) acc[j] = 0.f;
        const float* ur = sh_u + t*DIN;
        for (int dd = 0; dd < DIN; dd++) {
            float uv = ur[dd];
            const float4* xr = (const float4*)(sh_xp + dd*XD);  // 36 = 9*float4
#pragma unroll
            for (int q = 0; q < 9; q++) {
                float4 w4 = xr[q];
                acc[4*q+0] = fmaf(uv, w4.x, acc[4*q+0]);
                acc[4*q+1] = fmaf(uv, w4.y, acc[4*q+1]);
                acc[4*q+2] = fmaf(uv, w4.z, acc[4*q+2]);
                acc[4*q+3] = fmaf(uv, w4.w, acc[4*q+3]);
            }
        }
#pragma unroll
        for (int j = 0; j < XD; j++) sh_xd[t*XD + j] = acc[j];
    }
    __syncthreads();

    // ---- E: selective scan. 2 threads per channel (8 states each). ----
    {
        int d = tid >> 1, nh = tid & 1;
        float dtw0 = p.dtw[0*DIN+d], dtw1 = p.dtw[1*DIN+d];
        float dtw2 = p.dtw[2*DIN+d], dtw3 = p.dtw[3*DIN+d];
        float dtbv = p.dtb[d];
        float Dv   = p.D[d];
        float negA[8];
#pragma unroll
        for (int n = 0; n < 8; n++) negA[n] = -expf(p.Alog[d*DS + nh*8 + n]);
        float hs[8];
#pragma unroll
        for (int n = 0; n < 8; n++) hs[n] = 0.f;

        for (int t = 0; t < SEQ; t++) {
            const float* xr = sh_xd + t*XD;
            float dtraw = fmaf(xr[0],dtw0, fmaf(xr[1],dtw1,
                          fmaf(xr[2],dtw2, fmaf(xr[3],dtw3, dtbv))));
            float dt = (dtraw > 15.f) ? dtraw : log1pf(__expf(dtraw)); // softplus
            float ut = sh_u[t*DIN + d];
            float dtu = dt * ut;
            float part = 0.f;
#pragma unroll
            for (int n = 0; n < 8; n++) {
                float a = __expf(dt * negA[n]);
                hs[n] = fmaf(hs[n], a, dtu * xr[4 + nh*8 + n]);      // B
                part  = fmaf(hs[n], xr[20 + nh*8 + n], part);        // C dot
            }
            part += __shfl_xor_sync(0xffffffffu, part, 1);
            if (nh == 0) sh_u[t*DIN + d] = fmaf(ut, Dv, part);       // y = ys + u*D
        }
    }
    __syncthreads();

    // ---- F: stage outproj into dead SMEM; z-gate: y *= silu(h0 @ inproj[:,128:]) ----
    for (int i = tid; i < DIN*RED; i += 256) sh_op[i] = p.outproj[i];
    {
        int d = tid & 127, tg = tid >> 7;
        float wcol[RED];
#pragma unroll
        for (int k = 0; k < RED; k++) wcol[k] = p.inproj[k*256 + 128 + d];
        for (int t = tg; t < SEQ; t += 2) {
            const float4* hr = (const float4*)(sh_h0 + t*RED);
            float z = 0.f;
#pragma unroll
            for (int q = 0; q < 16; q++) {
                float4 h4 = hr[q];
                z = fmaf(h4.x, wcol[4*q+0], z);
                z = fmaf(h4.y, wcol[4*q+1], z);
                z = fmaf(h4.z, wcol[4*q+2], z);
                z = fmaf(h4.w, wcol[4*q+3], z);
            }
            float sz = z / (1.f + __expf(-z));
            sh_u[t*DIN + d] *= sz;
        }
    }
    __syncthreads();

    // ---- G: out = y @ outproj, scatter back un-reversed ----
    {
        float* ob = outbuf + (size_t)b * SEQ * RED;
        const float4* op4 = (const float4*)sh_op;
        for (int o = tid; o < SEQ*16; o += 256) {
            int t = o >> 4, j4 = o & 15;
            const float* yr = sh_u + t*DIN;
            float4 acc = {0.f,0.f,0.f,0.f};
#pragma unroll 8
            for (int dd = 0; dd < DIN; dd++) {
                float yv = yr[dd];
                float4 w4 = op4[dd*16 + j4];
                acc.x = fmaf(yv, w4.x, acc.x);
                acc.y = fmaf(yv, w4.y, acc.y);
                acc.z = fmaf(yv, w4.z, acc.z);
                acc.w = fmaf(yv, w4.w, acc.w);
            }
            int pt = dir ? (SEQ-1-t) : t;
            ((float4*)(ob + pt*RED))[j4] = acc;
        }
    }
}

// =================================================================
// Kernel 3: LN64(fw+bw)@ov_w+ov_b + x  ->  LN128 @ o_w + o_b -> out
// =================================================================
#define R3 8
#define POST_SMEM ((8192 + 16384 + R3*65 + 2*R3*129)*4)

__global__ void __launch_bounds__(256) post_kernel(
    const float* __restrict__ ovlnw, const float* __restrict__ ovlnb,
    const float* __restrict__ ovw,   const float* __restrict__ ovb,
    const float* __restrict__ olnw,  const float* __restrict__ olnb,
    const float* __restrict__ ow,    const float* __restrict__ obias,
    const float* __restrict__ xin,   float* __restrict__ out)
{
    extern __shared__ float sm[];
    float* s_ovw = sm;                       // 64*128
    float* s_ow  = sm + 8192;                // 128*128
    float* s_v   = sm + 24576;               // R3*65
    float* s_t   = sm + 24576 + R3*65;       // R3*129
    float* s_l   = sm + 24576 + R3*65 + R3*129;
    int tid = threadIdx.x;

    {
        const float4* s1 = (const float4*)ovw; float4* d1 = (float4*)s_ovw;
        for (int i = tid; i < 2048; i += 256) d1[i] = s1[i];
        const float4* s2 = (const float4*)ow;  float4* d2 = (float4*)s_ow;
        for (int i = tid; i < 4096; i += 256) d2[i] = s2[i];
    }
    int base = blockIdx.x * R3;
    int warp = tid >> 5, lane = tid & 31;

    // LN64 of (fw+bw): warp r handles row r
    {
        size_t row = (size_t)(base + warp);
        float v0 = g_dir0[row*RED + lane]      + g_dir1[row*RED + lane];
        float v1 = g_dir0[row*RED + 32 + lane] + g_dir1[row*RED + 32 + lane];
        float sum = v0 + v1, sq = v0*v0 + v1*v1;
#pragma unroll
        for (int off = 16; off; off >>= 1) {
            sum += __shfl_xor_sync(0xffffffffu, sum, off);
            sq  += __shfl_xor_sync(0xffffffffu, sq,  off);
        }
        float mean = sum * (1.f/64.f);
        float var  = sq  * (1.f/64.f) - mean*mean;
        float rstd = rsqrtf(var + 1e-5f);
        s_v[warp*65 + lane]      = (v0-mean)*rstd*ovlnw[lane]    + ovlnb[lane];
        s_v[warp*65 + 32 + lane] = (v1-mean)*rstd*ovlnw[32+lane] + ovlnb[32+lane];
    }
    __syncthreads();

    // GEMM1 (64->128) + residual
    {
        int r = tid >> 5, j4 = tid & 31;
        size_t row = (size_t)(base + r);
        float4 acc = ((const float4*)ovb)[j4];
        float4 xr  = ((const float4*)(xin + row*CC))[j4];
        acc.x += xr.x; acc.y += xr.y; acc.z += xr.z; acc.w += xr.w;
        const float4* w4p = (const float4*)s_ovw;
#pragma unroll 8
        for (int i = 0; i < 64; i++) {
            float lv = s_v[r*65 + i];
            float4 w4 = w4p[i*32 + j4];
            acc.x = fmaf(lv,w4.x,acc.x); acc.y = fmaf(lv,w4.y,acc.y);
            acc.z = fmaf(lv,w4.z,acc.z); acc.w = fmaf(lv,w4.w,acc.w);
        }
        s_t[r*129 + 4*j4+0] = acc.x; s_t[r*129 + 4*j4+1] = acc.y;
        s_t[r*129 + 4*j4+2] = acc.z; s_t[r*129 + 4*j4+3] = acc.w;
    }
    __syncthreads();

    // LN128: warp r handles row r
    {
        int r = warp;
        float v[4]; float sum = 0.f, sq = 0.f;
#pragma unroll
        for (int k = 0; k < 4; k++) {
            v[k] = s_t[r*129 + lane + 32*k];
            sum += v[k]; sq += v[k]*v[k];
        }
#pragma unroll
        for (int off = 16; off; off >>= 1) {
            sum += __shfl_xor_sync(0xffffffffu, sum, off);
            sq  += __shfl_xor_sync(0xffffffffu, sq,  off);
        }
        float mean = sum * (1.f/128.f);
        float var  = sq  * (1.f/128.f) - mean*mean;
        float rstd = rsqrtf(var + 1e-5f);
#pragma unroll
        for (int k = 0; k < 4; k++) {
            int i = lane + 32*k;
            s_l[r*129 + i] = (v[k]-mean)*rstd*olnw[i] + olnb[i];
        }
    }
    __syncthreads();

    // GEMM2 (128->128)
    {
        int r = tid >> 5, j4 = tid & 31;
        size_t row = (size_t)(base + r);
        float4 acc = ((const float4*)obias)[j4];
        const float4* w4p = (const float4*)s_ow;
#pragma unroll 8
        for (int i = 0; i < CC; i++) {
            float lv = s_l[r*129 + i];
            float4 w4 = w4p[i*32 + j4];
            acc.x = fmaf(lv,w4.x,acc.x); acc.y = fmaf(lv,w4.y,acc.y);
            acc.z = fmaf(lv,w4.z,acc.z); acc.w = fmaf(lv,w4.w,acc.w);
        }
        ((float4*)(out + row*CC))[j4] = acc;
    }
}

// =================================================================
extern "C" void kernel_launch(void* const* d_in, const int* in_sizes, int n_in,
                              void* d_out, int out_size)
{
    (void)n_in; (void)out_size;

    // Two plausible serializations of setup_inputs():
    //  - dict insertion order: x,qk,in_ln_w,in_ln_b,in_w,in_b,
    //        ov_ln_w,ov_ln_b,ov_w,ov_b,o_ln_w,o_ln_b,o_w,o_b, fw_*(9), bw_*(9)
    //  - reference() signature order: x,qk,in_ln_w,in_ln_b,in_w,in_b,
    //        fw_*(9), bw_*(9), ov_ln_w,...,o_b
    // Disambiguate at runtime: slot 6 is ov_ln_w (64 elems) in dict order,
    // fw_inproj (16384 elems) in signature order.
    bool sig_order = (in_sizes[6] > 1024);

    int i_ovlnw, i_fw, i_bw;
    if (sig_order) { i_fw = 6;  i_bw = 15; i_ovlnw = 24; }
    else           { i_ovlnw = 6; i_fw = 14; i_bw = 23; }

    const float* x     = (const float*)d_in[0];
    const float* qk    = (const float*)d_in[1];
    const float* inlnw = (const float*)d_in[2];
    const float* inlnb = (const float*)d_in[3];
    const float* inw   = (const float*)d_in[4];
    const float* inb   = (const float*)d_in[5];

    MambaW wf { (const float*)d_in[i_fw+0], (const float*)d_in[i_fw+1], (const float*)d_in[i_fw+2],
                (const float*)d_in[i_fw+3], (const float*)d_in[i_fw+4], (const float*)d_in[i_fw+5],
                (const float*)d_in[i_fw+6], (const float*)d_in[i_fw+7], (const float*)d_in[i_fw+8] };
    MambaW wb { (const float*)d_in[i_bw+0], (const float*)d_in[i_bw+1], (const float*)d_in[i_bw+2],
                (const float*)d_in[i_bw+3], (const float*)d_in[i_bw+4], (const float*)d_in[i_bw+5],
                (const float*)d_in[i_bw+6], (const float*)d_in[i_bw+7], (const float*)d_in[i_bw+8] };

    const float* ovlnw = (const float*)d_in[i_ovlnw+0];
    const float* ovlnb = (const float*)d_in[i_ovlnw+1];
    const float* ovw   = (const float*)d_in[i_ovlnw+2];
    const float* ovb   = (const float*)d_in[i_ovlnw+3];
    const float* olnw  = (const float*)d_in[i_ovlnw+4];
    const float* olnb  = (const float*)d_in[i_ovlnw+5];
    const float* ow    = (const float*)d_in[i_ovlnw+6];
    const float* obias = (const float*)d_in[i_ovlnw+7];

    cudaFuncSetAttribute(pre_kernel,   cudaFuncAttributeMaxDynamicSharedMemorySize, PRE_SMEM);
    cudaFuncSetAttribute(mamba_kernel, cudaFuncAttributeMaxDynamicSharedMemorySize, MAMBA_SMEM);
    cudaFuncSetAttribute(post_kernel,  cudaFuncAttributeMaxDynamicSharedMemorySize, POST_SMEM);

    pre_kernel  <<<NROWS/R1, 256, PRE_SMEM  >>>(x, qk, inlnw, inlnb, inw, inb);
    mamba_kernel<<<2*BT,     256, MAMBA_SMEM>>>(wf, wb);
    post_kernel <<<NROWS/R3, 256, POST_SMEM >>>(ovlnw, ovlnb, ovw, ovb,
                                                olnw, olnb, ow, obias,
                                                x, (float*)d_out);
}